// round 3
// baseline (speedup 1.0000x reference)
#include <cuda_runtime.h>

// AI4DEM coupling_backward: 3x3 tent-spline gather, 4096x4096 periodic grid.
// Inputs (metadata order): xp, yp, x_grid(unused), y_grid(unused), vx, vy, Fx, Fy, mask
// Output: 5 planes [alpha, alpha_u, alpha_v, Fx, Fy], each 4096*4096 f32.
//
// Reference reduces to (DX=DY=1, inv_area=1):
//   per tap: w = max(0,1-|xp_src - x_dst|) * max(0,1-|yp_src - y_dst|)
//   out     = mask_dst * VP * sum(w * field_src)     <-- mask at DESTINATION
//
// R3 change: halo columns come from warp shuffles of the neighbor lane's
// float4 instead of two fully-active scalar LDGs (which cost 8 L1 wavefronts
// per field-row for 2 useful floats/warp). Only lanes 0 and 31 do a
// predicated scalar load for the warp-edge halo (periodic wrap).

#define NXD 4096
#define MASKW 4095
#define FULLM 0xffffffffu

__device__ __forceinline__ void load6s(const float* __restrict__ p, size_t rb,
                                       int xb, int cl, int cr, int lane,
                                       float v[6]) {
    float4 q = *reinterpret_cast<const float4*>(p + rb + xb);
    // warp-edge halo: one LDG with 2 active lanes (lane 0 -> left, 31 -> right)
    float hv = 0.0f;
    int   hc = (lane == 0) ? cl : cr;
    if ((lane == 0) | (lane == 31)) hv = __ldg(p + rb + hc);
    float ls = __shfl_up_sync(FULLM, q.w, 1);    // lane l-1's q.w = col xb-1
    float rs = __shfl_down_sync(FULLM, q.x, 1);  // lane l+1's q.x = col xb+4
    v[0] = (lane == 0)  ? hv : ls;
    v[5] = (lane == 31) ? hv : rs;
    v[1] = q.x; v[2] = q.y; v[3] = q.z; v[4] = q.w;
}

__global__ void __launch_bounds__(256)
ai4dem_kernel(const float* __restrict__ xp, const float* __restrict__ yp,
              const float* __restrict__ vx, const float* __restrict__ vy,
              const float* __restrict__ Fx, const float* __restrict__ Fy,
              const float* __restrict__ mk, float* __restrict__ out)
{
    const float VP = 3.1415f / 6.0f;

    int t    = blockIdx.x * blockDim.x + threadIdx.x;  // 4096*1024 threads
    int y    = t >> 10;                                // row
    int xb   = (t & 1023) << 2;                        // base column (x4)
    int lane = threadIdx.x & 31;

    const float fy0 = (float)y;
    float xk0 = (float)xb;
    float xdst[4] = {xk0, xk0 + 1.0f, xk0 + 2.0f, xk0 + 3.0f};

    float aA[4] = {0.f, 0.f, 0.f, 0.f};
    float aU[4] = {0.f, 0.f, 0.f, 0.f};
    float aV[4] = {0.f, 0.f, 0.f, 0.f};
    float aX[4] = {0.f, 0.f, 0.f, 0.f};
    float aY[4] = {0.f, 0.f, 0.f, 0.f};

    int cl = (xb - 1) & MASKW;   // used by lane 0 only
    int cr = (xb + 4) & MASKW;   // used by lane 31 only

    #pragma unroll
    for (int r = 0; r < 3; ++r) {
        int ys = (y + r - 1) & MASKW;
        size_t rb = (size_t)ys << 12;

        float xps[6], yps[6], vxs[6], vys[6], fxs[6], fys[6];
        load6s(xp, rb, xb, cl, cr, lane, xps);
        load6s(yp, rb, xb, cl, cr, lane, yps);
        load6s(vx, rb, xb, cl, cr, lane, vxs);
        load6s(vy, rb, xb, cl, cr, lane, vys);
        load6s(Fx, rb, xb, cl, cr, lane, fxs);
        load6s(Fy, rb, xb, cl, cr, lane, fys);

        #pragma unroll
        for (int s = 0; s < 6; ++s) {
            float dyv = yps[s] - fy0;
            float ny  = fmaxf(1.0f - fabsf(dyv), 0.0f);

            const int kmin = (s - 2 > 0) ? (s - 2) : 0;
            const int kmax = (s < 3) ? s : 3;
            #pragma unroll
            for (int k = kmin; k <= kmax; ++k) {
                float dxv = xps[s] - xdst[k];
                float nx  = fmaxf(1.0f - fabsf(dxv), 0.0f);
                float w   = ny * nx;
                aA[k] += w;
                aU[k] = fmaf(w, vxs[s], aU[k]);
                aV[k] = fmaf(w, vys[s], aV[k]);
                aX[k] = fmaf(w, fxs[s], aX[k]);
                aY[k] = fmaf(w, fys[s], aY[k]);
            }
        }
    }

    // Destination-side factor: mask_dst * VP (mask is NOT rolled in the ref).
    size_t o = ((size_t)y << 12) + xb;
    float4 mq = *reinterpret_cast<const float4*>(mk + o);
    float md[4] = {mq.x * VP, mq.y * VP, mq.z * VP, mq.w * VP};

    #pragma unroll
    for (int k = 0; k < 4; ++k) {
        aA[k] *= md[k]; aU[k] *= md[k]; aV[k] *= md[k];
        aX[k] *= md[k]; aY[k] *= md[k];
    }

    const size_t P = (size_t)NXD * NXD;
    *reinterpret_cast<float4*>(out + o)         = make_float4(aA[0], aA[1], aA[2], aA[3]);
    *reinterpret_cast<float4*>(out + P + o)     = make_float4(aU[0], aU[1], aU[2], aU[3]);
    *reinterpret_cast<float4*>(out + 2 * P + o) = make_float4(aV[0], aV[1], aV[2], aV[3]);
    *reinterpret_cast<float4*>(out + 3 * P + o) = make_float4(aX[0], aX[1], aX[2], aX[3]);
    *reinterpret_cast<float4*>(out + 4 * P + o) = make_float4(aY[0], aY[1], aY[2], aY[3]);
}

extern "C" void kernel_launch(void* const* d_in, const int* in_sizes, int n_in,
                              void* d_out, int out_size)
{
    const float* xp = (const float*)d_in[0];
    const float* yp = (const float*)d_in[1];
    // d_in[2] = x_grid, d_in[3] = y_grid: analytic (x, y), not needed.
    const float* vx = (const float*)d_in[4];
    const float* vy = (const float*)d_in[5];
    const float* Fx = (const float*)d_in[6];
    const float* Fy = (const float*)d_in[7];
    const float* mk = (const float*)d_in[8];
    float* out = (float*)d_out;

    const int total = 4096 * 1024;     // one thread per 4 outputs
    const int block = 256;
    ai4dem_kernel<<<total / block, block>>>(xp, yp, vx, vy, Fx, Fy, mk, out);
}

// round 4
// speedup vs baseline: 1.2533x; 1.2533x over previous
#include <cuda_runtime.h>

// AI4DEM coupling_backward: 3x3 tent-spline gather, 4096x4096 periodic grid.
// Inputs: xp, yp, x_grid(unused), y_grid(unused), vx, vy, Fx, Fy, mask
// Output: 5 planes [alpha, alpha_u, alpha_v, Fx, Fy], each 4096*4096 f32.
//
//   per tap: w = max(0,1-|xp_src - x_dst|) * max(0,1-|yp_src - y_dst|)
//   out     = mask_dst * VP * sum(w * field_src)     (mask at DESTINATION)
//
// R4: each thread computes a 2x4 output tile (2 rows x 4 cols). The union of
// source rows for both output rows is 4 (y0-1..y0+2), so per field we load
// 4 rows x 6 cols instead of 2x(3 rows x 6 cols): 33% fewer L1 wavefronts
// per output, with all loads independent (no shuffle serialization — R3's
// mistake). Dead (src-row, dst-row) pairs (|row gap| >= 2) are skipped at
// compile time.

#define NXD 4096
#define MASKW 4095

__device__ __forceinline__ void load6(const float* __restrict__ p, size_t rb,
                                      int xb, int cl, int cr, float v[6]) {
    float4 q = *reinterpret_cast<const float4*>(p + rb + xb);
    v[0] = __ldg(p + rb + cl);
    v[1] = q.x; v[2] = q.y; v[3] = q.z; v[4] = q.w;
    v[5] = __ldg(p + rb + cr);
}

__global__ void __launch_bounds__(256)
ai4dem_kernel(const float* __restrict__ xp, const float* __restrict__ yp,
              const float* __restrict__ vx, const float* __restrict__ vy,
              const float* __restrict__ Fx, const float* __restrict__ Fy,
              const float* __restrict__ mk, float* __restrict__ out)
{
    const float VP = 3.1415f / 6.0f;

    int t  = blockIdx.x * blockDim.x + threadIdx.x;   // 2048*1024 threads
    int yp2 = t >> 10;                                // row-pair index
    int xb  = (t & 1023) << 2;                        // base column (x4)
    int y0  = yp2 << 1;

    const float fy[2] = {(float)y0, (float)(y0 + 1)};
    float xk0 = (float)xb;
    float xdst[4] = {xk0, xk0 + 1.0f, xk0 + 2.0f, xk0 + 3.0f};

    float aA[2][4] = {{0.f,0.f,0.f,0.f},{0.f,0.f,0.f,0.f}};
    float aU[2][4] = {{0.f,0.f,0.f,0.f},{0.f,0.f,0.f,0.f}};
    float aV[2][4] = {{0.f,0.f,0.f,0.f},{0.f,0.f,0.f,0.f}};
    float aX[2][4] = {{0.f,0.f,0.f,0.f},{0.f,0.f,0.f,0.f}};
    float aY[2][4] = {{0.f,0.f,0.f,0.f},{0.f,0.f,0.f,0.f}};

    int cl = (xb - 1) & MASKW;
    int cr = (xb + 4) & MASKW;

    #pragma unroll
    for (int r = 0; r < 4; ++r) {                     // src rows y0-1 .. y0+2
        int ys = (y0 + r - 1) & MASKW;
        size_t rb = (size_t)ys << 12;

        float xps[6], yps[6], vxs[6], vys[6], fxs[6], fys[6];
        load6(xp, rb, xb, cl, cr, xps);
        load6(yp, rb, xb, cl, cr, yps);
        load6(vx, rb, xb, cl, cr, vxs);
        load6(vy, rb, xb, cl, cr, vys);
        load6(Fx, rb, xb, cl, cr, fxs);
        load6(Fy, rb, xb, cl, cr, fys);

        // tent support: src row r reaches dst rows within distance 1
        const int dmin = (r == 3) ? 1 : 0;
        const int dmax = (r == 0) ? 0 : 1;

        #pragma unroll
        for (int s = 0; s < 6; ++s) {
            float ny[2];
            #pragma unroll
            for (int d = dmin; d <= dmax; ++d)
                ny[d] = fmaxf(1.0f - fabsf(yps[s] - fy[d]), 0.0f);

            const int kmin = (s - 2 > 0) ? (s - 2) : 0;
            const int kmax = (s < 3) ? s : 3;
            #pragma unroll
            for (int k = kmin; k <= kmax; ++k) {
                float dxv = xps[s] - xdst[k];
                float nx  = fmaxf(1.0f - fabsf(dxv), 0.0f);
                #pragma unroll
                for (int d = dmin; d <= dmax; ++d) {
                    float w = ny[d] * nx;
                    aA[d][k] += w;
                    aU[d][k] = fmaf(w, vxs[s], aU[d][k]);
                    aV[d][k] = fmaf(w, vys[s], aV[d][k]);
                    aX[d][k] = fmaf(w, fxs[s], aX[d][k]);
                    aY[d][k] = fmaf(w, fys[s], aY[d][k]);
                }
            }
        }
    }

    const size_t P = (size_t)NXD * NXD;
    #pragma unroll
    for (int d = 0; d < 2; ++d) {
        size_t o = ((size_t)(y0 + d) << 12) + xb;
        float4 mq = *reinterpret_cast<const float4*>(mk + o);
        float md[4] = {mq.x * VP, mq.y * VP, mq.z * VP, mq.w * VP};

        #pragma unroll
        for (int k = 0; k < 4; ++k) {
            aA[d][k] *= md[k]; aU[d][k] *= md[k]; aV[d][k] *= md[k];
            aX[d][k] *= md[k]; aY[d][k] *= md[k];
        }

        *reinterpret_cast<float4*>(out + o)         = make_float4(aA[d][0], aA[d][1], aA[d][2], aA[d][3]);
        *reinterpret_cast<float4*>(out + P + o)     = make_float4(aU[d][0], aU[d][1], aU[d][2], aU[d][3]);
        *reinterpret_cast<float4*>(out + 2 * P + o) = make_float4(aV[d][0], aV[d][1], aV[d][2], aV[d][3]);
        *reinterpret_cast<float4*>(out + 3 * P + o) = make_float4(aX[d][0], aX[d][1], aX[d][2], aX[d][3]);
        *reinterpret_cast<float4*>(out + 4 * P + o) = make_float4(aY[d][0], aY[d][1], aY[d][2], aY[d][3]);
    }
}

extern "C" void kernel_launch(void* const* d_in, const int* in_sizes, int n_in,
                              void* d_out, int out_size)
{
    const float* xp = (const float*)d_in[0];
    const float* yp = (const float*)d_in[1];
    // d_in[2] = x_grid, d_in[3] = y_grid: analytic (x, y), not needed.
    const float* vx = (const float*)d_in[4];
    const float* vy = (const float*)d_in[5];
    const float* Fx = (const float*)d_in[6];
    const float* Fy = (const float*)d_in[7];
    const float* mk = (const float*)d_in[8];
    float* out = (float*)d_out;

    const int total = 2048 * 1024;     // one thread per 2x4 output tile
    const int block = 256;
    ai4dem_kernel<<<total / block, block>>>(xp, yp, vx, vy, Fx, Fy, mk, out);
}

// round 6
// speedup vs baseline: 1.2729x; 1.0156x over previous
#include <cuda_runtime.h>

// AI4DEM coupling_backward: 3x3 tent-spline gather, 4096x4096 periodic grid.
// Inputs: xp, yp, x_grid(unused), y_grid(unused), vx, vy, Fx, Fy, mask
// Output: 5 planes [alpha, alpha_u, alpha_v, Fx, Fy], each 4096*4096 f32.
//
//   per tap: w = max(0,1-|xp_src - x_dst|) * max(0,1-|yp_src - y_dst|)
//   out     = mask_dst * VP * sum(w * field_src)     (mask at DESTINATION)
//
// R5: same 2x4 output tile as R4 (best L1-wavefront economy: union of 4 src
// rows serves 2 dst rows), but restructured for register pressure: per src
// row we first materialize the 12 nonzero x-weights nx[s][k] and 12
// y-weights ny[d][s] (xp/yp registers die), then stream the 4 data fields
// through in two batches. __launch_bounds__(256,3) enforces <=85 regs ->
// 24 warps/SM (vs 14 in R4, which was latency-bound at occ 22%).

#define NXD 4096
#define MASKW 4095

__device__ __forceinline__ void load6(const float* __restrict__ p, size_t rb,
                                      int xb, int cl, int cr, float v[6]) {
    float4 q = *reinterpret_cast<const float4*>(p + rb + xb);
    v[0] = __ldg(p + rb + cl);
    v[1] = q.x; v[2] = q.y; v[3] = q.z; v[4] = q.w;
    v[5] = __ldg(p + rb + cr);
}

__device__ __forceinline__ float tent(float d) {
    return fmaxf(1.0f - fabsf(d), 0.0f);
}

// flattened index of the 12 nonzero (s,k) pairs: s=0:k0 | s=1:k0,1 | s=2:k0,1,2
// | s=3:k1,2,3 | s=4:k2,3 | s=5:k3
__device__ __forceinline__ constexpr int kmin_of(int s) { return (s - 2 > 0) ? (s - 2) : 0; }
__device__ __forceinline__ constexpr int kmax_of(int s) { return (s < 3) ? s : 3; }

__global__ void __launch_bounds__(256, 3)
ai4dem_kernel(const float* __restrict__ xp, const float* __restrict__ yp,
              const float* __restrict__ vx, const float* __restrict__ vy,
              const float* __restrict__ Fx, const float* __restrict__ Fy,
              const float* __restrict__ mk, float* __restrict__ out)
{
    const float VP = 3.1415f / 6.0f;

    int t   = blockIdx.x * blockDim.x + threadIdx.x;  // 2048*1024 threads
    int yp2 = t >> 10;                                // row-pair index
    int xb  = (t & 1023) << 2;                        // base column (x4)
    int y0  = yp2 << 1;

    const float fy0 = (float)y0;
    const float fy1 = (float)(y0 + 1);
    float xk0 = (float)xb;
    float xdst[4] = {xk0, xk0 + 1.0f, xk0 + 2.0f, xk0 + 3.0f};

    float aA[2][4] = {{0.f,0.f,0.f,0.f},{0.f,0.f,0.f,0.f}};
    float aU[2][4] = {{0.f,0.f,0.f,0.f},{0.f,0.f,0.f,0.f}};
    float aV[2][4] = {{0.f,0.f,0.f,0.f},{0.f,0.f,0.f,0.f}};
    float aX[2][4] = {{0.f,0.f,0.f,0.f},{0.f,0.f,0.f,0.f}};
    float aY[2][4] = {{0.f,0.f,0.f,0.f},{0.f,0.f,0.f,0.f}};

    int cl = (xb - 1) & MASKW;
    int cr = (xb + 4) & MASKW;

    #pragma unroll
    for (int r = 0; r < 4; ++r) {                     // src rows y0-1 .. y0+2
        int ys = (y0 + r - 1) & MASKW;
        size_t rb = (size_t)ys << 12;

        // tent support: src row r reaches dst rows within distance 1
        const int dmin = (r == 3) ? 1 : 0;
        const int dmax = (r == 0) ? 0 : 1;

        // batch 1: coordinates + first two fields (high MLP, then xp/yp die)
        float xps[6], yps[6], vxs[6], vys[6];
        load6(xp, rb, xb, cl, cr, xps);
        load6(yp, rb, xb, cl, cr, yps);
        load6(vx, rb, xb, cl, cr, vxs);
        load6(vy, rb, xb, cl, cr, vys);

        // materialize weights; xp/yp registers are dead afterwards
        float ny[2][6];
        float nx[12];
        {
            int idx = 0;
            #pragma unroll
            for (int s = 0; s < 6; ++s) {
                #pragma unroll
                for (int d = dmin; d <= dmax; ++d)
                    ny[d][s] = tent(yps[s] - (d ? fy1 : fy0));
                #pragma unroll
                for (int k = kmin_of(s); k <= kmax_of(s); ++k)
                    nx[idx++] = tent(xps[s] - xdst[k]);
            }
        }

        // alpha + vx + vy accumulation (Fx/Fy loads issue underneath)
        float fxs[6], fys[6];
        load6(Fx, rb, xb, cl, cr, fxs);
        load6(Fy, rb, xb, cl, cr, fys);

        {
            int idx = 0;
            #pragma unroll
            for (int s = 0; s < 6; ++s) {
                const int i0 = idx;
                #pragma unroll
                for (int d = dmin; d <= dmax; ++d) {
                    float n  = ny[d][s];
                    float tu = n * vxs[s];
                    float tv = n * vys[s];
                    int ii = i0;
                    #pragma unroll
                    for (int k = kmin_of(s); k <= kmax_of(s); ++k, ++ii) {
                        float w = nx[ii];
                        aA[d][k] = fmaf(w, n,  aA[d][k]);
                        aU[d][k] = fmaf(w, tu, aU[d][k]);
                        aV[d][k] = fmaf(w, tv, aV[d][k]);
                    }
                }
                idx += kmax_of(s) - kmin_of(s) + 1;
            }
        }

        // Fx + Fy accumulation
        {
            int idx = 0;
            #pragma unroll
            for (int s = 0; s < 6; ++s) {
                const int i0 = idx;
                #pragma unroll
                for (int d = dmin; d <= dmax; ++d) {
                    float n  = ny[d][s];
                    float tx = n * fxs[s];
                    float ty = n * fys[s];
                    int ii = i0;
                    #pragma unroll
                    for (int k = kmin_of(s); k <= kmax_of(s); ++k, ++ii) {
                        float w = nx[ii];
                        aX[d][k] = fmaf(w, tx, aX[d][k]);
                        aY[d][k] = fmaf(w, ty, aY[d][k]);
                    }
                }
                idx += kmax_of(s) - kmin_of(s) + 1;
            }
        }
    }

    const size_t P = (size_t)NXD * NXD;
    #pragma unroll
    for (int d = 0; d < 2; ++d) {
        size_t o = ((size_t)(y0 + d) << 12) + xb;
        float4 mq = *reinterpret_cast<const float4*>(mk + o);
        float md[4] = {mq.x * VP, mq.y * VP, mq.z * VP, mq.w * VP};

        #pragma unroll
        for (int k = 0; k < 4; ++k) {
            aA[d][k] *= md[k]; aU[d][k] *= md[k]; aV[d][k] *= md[k];
            aX[d][k] *= md[k]; aY[d][k] *= md[k];
        }

        *reinterpret_cast<float4*>(out + o)         = make_float4(aA[d][0], aA[d][1], aA[d][2], aA[d][3]);
        *reinterpret_cast<float4*>(out + P + o)     = make_float4(aU[d][0], aU[d][1], aU[d][2], aU[d][3]);
        *reinterpret_cast<float4*>(out + 2 * P + o) = make_float4(aV[d][0], aV[d][1], aV[d][2], aV[d][3]);
        *reinterpret_cast<float4*>(out + 3 * P + o) = make_float4(aX[d][0], aX[d][1], aX[d][2], aX[d][3]);
        *reinterpret_cast<float4*>(out + 4 * P + o) = make_float4(aY[d][0], aY[d][1], aY[d][2], aY[d][3]);
    }
}

extern "C" void kernel_launch(void* const* d_in, const int* in_sizes, int n_in,
                              void* d_out, int out_size)
{
    const float* xp = (const float*)d_in[0];
    const float* yp = (const float*)d_in[1];
    // d_in[2] = x_grid, d_in[3] = y_grid: analytic (x, y), not needed.
    const float* vx = (const float*)d_in[4];
    const float* vy = (const float*)d_in[5];
    const float* Fx = (const float*)d_in[6];
    const float* Fy = (const float*)d_in[7];
    const float* mk = (const float*)d_in[8];
    float* out = (float*)d_out;

    const int total = 2048 * 1024;     // one thread per 2x4 output tile
    const int block = 256;
    ai4dem_kernel<<<total / block, block>>>(xp, yp, vx, vy, Fx, Fy, mk, out);
}

// round 7
// speedup vs baseline: 1.3541x; 1.0638x over previous
#include <cuda_runtime.h>
#include <cstdint>

// AI4DEM coupling_backward: 3x3 tent-spline gather, 4096x4096 periodic grid.
// Inputs: xp, yp, x_grid(unused), y_grid(unused), vx, vy, Fx, Fy, mask
// Output: 5 planes [alpha, alpha_u, alpha_v, Fx, Fy], each 4096*4096 f32.
//
//   per tap: w = max(0,1-|xp_src - x_dst|) * max(0,1-|yp_src - y_dst|)
//   out     = mask_dst * VP * sum(w * field_src)     (mask at DESTINATION)
//
// R7: block (128 thr) stages a 10-row x 136-col x 6-field source tile into
// smem via cp.async.cg (no registers consumed, no L1 pollution, one barrier),
// then each thread computes a 2x4 output tile reading from smem. This
// removes both prior bottlenecks at once: L1 global wavefronts drop ~5x
// (halo scalar LDGs were 2/3 of them) and loads no longer occupy registers.

#define NXD   4096
#define MASKW 4095

#define BLK_T    128          // threads per block
#define OUT_ROWS 8            // output rows per block
#define SRC_ROWS 10           // OUT_ROWS + 2 halo rows
#define ROWW     136          // 4 pad | 128 main | 4 pad  (floats)
#define ROWVECS  34           // ROWW / 4 float4s per field-row
#define VECS_PER_FIELD (SRC_ROWS * ROWVECS)   // 340

__device__ __forceinline__ void cpa16(uint32_t saddr, const float* g) {
    asm volatile("cp.async.cg.shared.global [%0], [%1], 16;\n"
                 :: "r"(saddr), "l"(g));
}

__device__ __forceinline__ float tent(float d) {
    return fmaxf(1.0f - fabsf(d), 0.0f);
}

__device__ __forceinline__ constexpr int kmin_of(int s) { return (s - 2 > 0) ? (s - 2) : 0; }
__device__ __forceinline__ constexpr int kmax_of(int s) { return (s < 3) ? s : 3; }

__global__ void __launch_bounds__(BLK_T, 6)
ai4dem_kernel(const float* __restrict__ xp, const float* __restrict__ yp,
              const float* __restrict__ vx, const float* __restrict__ vy,
              const float* __restrict__ Fx, const float* __restrict__ Fy,
              const float* __restrict__ mk, float* __restrict__ out)
{
    const float VP = 3.1415f / 6.0f;

    __shared__ float sm[6][SRC_ROWS][ROWW];   // 32,640 bytes

    const int t   = threadIdx.x;
    const int bx  = blockIdx.x & 31;          // 32 col-blocks
    const int by  = blockIdx.x >> 5;          // 512 row-blocks
    const int xb0 = bx << 7;                  // block's first col
    const int y0b = by << 3;                  // block's first out row

    // ---- stage 6 fields x 10 rows x 136 cols via cp.async ----
    {
        const float* fptr[6] = {xp, yp, vx, vy, Fx, Fy};
        #pragma unroll
        for (int f = 0; f < 6; ++f) {
            const float* base = fptr[f];
            #pragma unroll
            for (int j = t; j < VECS_PER_FIELD; j += BLK_T) {
                int rr = j / ROWVECS;                 // 0..9
                int v  = j - rr * ROWVECS;            // 0..33
                int gy = (y0b - 1 + rr) & MASKW;
                int gx = (xb0 - 4 + (v << 2)) & MASKW;   // 16B-aligned, wraps whole
                uint32_t sa = (uint32_t)__cvta_generic_to_shared(&sm[f][rr][v << 2]);
                cpa16(sa, base + ((size_t)gy << 12) + gx);
            }
        }
        asm volatile("cp.async.commit_group;\n" ::: "memory");
        asm volatile("cp.async.wait_group 0;\n" ::: "memory");
        __syncthreads();
    }

    // ---- compute: each thread a 2x4 output tile ----
    const int tx = t & 31;                    // col quad within block
    const int ty = t >> 5;                    // row pair within block (0..3)
    const int xl = tx << 2;                   // local col offset
    const int xb = xb0 + xl;                  // global base col
    const int y0 = y0b + (ty << 1);           // global first out row

    const float fy0 = (float)y0;
    const float fy1 = (float)(y0 + 1);
    const float xk0 = (float)xb;
    const float xdst[4] = {xk0, xk0 + 1.0f, xk0 + 2.0f, xk0 + 3.0f};

    float aA[2][4] = {{0.f,0.f,0.f,0.f},{0.f,0.f,0.f,0.f}};
    float aU[2][4] = {{0.f,0.f,0.f,0.f},{0.f,0.f,0.f,0.f}};
    float aV[2][4] = {{0.f,0.f,0.f,0.f},{0.f,0.f,0.f,0.f}};
    float aX[2][4] = {{0.f,0.f,0.f,0.f},{0.f,0.f,0.f,0.f}};
    float aY[2][4] = {{0.f,0.f,0.f,0.f},{0.f,0.f,0.f,0.f}};

    #pragma unroll
    for (int r = 0; r < 4; ++r) {             // src rows y0-1 .. y0+2
        const int sr = (ty << 1) + r;         // smem row 0..9

        // tent support: src row r reaches dst rows within distance 1
        const int dmin = (r == 3) ? 1 : 0;
        const int dmax = (r == 0) ? 0 : 1;

        // coords -> weights (xp/yp regs die immediately)
        float ny[2][6];
        float nx[12];
        {
            float4 qx = *reinterpret_cast<const float4*>(&sm[0][sr][4 + xl]);
            float xl0 = sm[0][sr][3 + xl], xr0 = sm[0][sr][8 + xl];
            float4 qy = *reinterpret_cast<const float4*>(&sm[1][sr][4 + xl]);
            float yl0 = sm[1][sr][3 + xl], yr0 = sm[1][sr][8 + xl];
            float xps[6] = {xl0, qx.x, qx.y, qx.z, qx.w, xr0};
            float yps[6] = {yl0, qy.x, qy.y, qy.z, qy.w, yr0};
            int idx = 0;
            #pragma unroll
            for (int s = 0; s < 6; ++s) {
                #pragma unroll
                for (int d = dmin; d <= dmax; ++d)
                    ny[d][s] = tent(yps[s] - (d ? fy1 : fy0));
                #pragma unroll
                for (int k = kmin_of(s); k <= kmax_of(s); ++k)
                    nx[idx++] = tent(xps[s] - xdst[k]);
            }
        }

        // vx / vy + alpha
        {
            float4 qu = *reinterpret_cast<const float4*>(&sm[2][sr][4 + xl]);
            float ul = sm[2][sr][3 + xl], ur = sm[2][sr][8 + xl];
            float4 qv = *reinterpret_cast<const float4*>(&sm[3][sr][4 + xl]);
            float vl = sm[3][sr][3 + xl], vr = sm[3][sr][8 + xl];
            float vxs[6] = {ul, qu.x, qu.y, qu.z, qu.w, ur};
            float vys[6] = {vl, qv.x, qv.y, qv.z, qv.w, vr};
            int idx = 0;
            #pragma unroll
            for (int s = 0; s < 6; ++s) {
                const int i0 = idx;
                #pragma unroll
                for (int d = dmin; d <= dmax; ++d) {
                    float n  = ny[d][s];
                    float tu = n * vxs[s];
                    float tv = n * vys[s];
                    int ii = i0;
                    #pragma unroll
                    for (int k = kmin_of(s); k <= kmax_of(s); ++k, ++ii) {
                        float w = nx[ii];
                        aA[d][k] = fmaf(w, n,  aA[d][k]);
                        aU[d][k] = fmaf(w, tu, aU[d][k]);
                        aV[d][k] = fmaf(w, tv, aV[d][k]);
                    }
                }
                idx += kmax_of(s) - kmin_of(s) + 1;
            }
        }

        // Fx / Fy
        {
            float4 qa = *reinterpret_cast<const float4*>(&sm[4][sr][4 + xl]);
            float al = sm[4][sr][3 + xl], ar = sm[4][sr][8 + xl];
            float4 qb = *reinterpret_cast<const float4*>(&sm[5][sr][4 + xl]);
            float bl = sm[5][sr][3 + xl], br = sm[5][sr][8 + xl];
            float fxs[6] = {al, qa.x, qa.y, qa.z, qa.w, ar};
            float fys[6] = {bl, qb.x, qb.y, qb.z, qb.w, br};
            int idx = 0;
            #pragma unroll
            for (int s = 0; s < 6; ++s) {
                const int i0 = idx;
                #pragma unroll
                for (int d = dmin; d <= dmax; ++d) {
                    float n  = ny[d][s];
                    float txv = n * fxs[s];
                    float tyv = n * fys[s];
                    int ii = i0;
                    #pragma unroll
                    for (int k = kmin_of(s); k <= kmax_of(s); ++k, ++ii) {
                        float w = nx[ii];
                        aX[d][k] = fmaf(w, txv, aX[d][k]);
                        aY[d][k] = fmaf(w, tyv, aY[d][k]);
                    }
                }
                idx += kmax_of(s) - kmin_of(s) + 1;
            }
        }
    }

    // ---- mask (at destination) * VP, then store 5 planes ----
    const size_t P = (size_t)NXD * NXD;
    #pragma unroll
    for (int d = 0; d < 2; ++d) {
        size_t o = ((size_t)(y0 + d) << 12) + xb;
        float4 mq = *reinterpret_cast<const float4*>(mk + o);
        float md[4] = {mq.x * VP, mq.y * VP, mq.z * VP, mq.w * VP};

        #pragma unroll
        for (int k = 0; k < 4; ++k) {
            aA[d][k] *= md[k]; aU[d][k] *= md[k]; aV[d][k] *= md[k];
            aX[d][k] *= md[k]; aY[d][k] *= md[k];
        }

        *reinterpret_cast<float4*>(out + o)         = make_float4(aA[d][0], aA[d][1], aA[d][2], aA[d][3]);
        *reinterpret_cast<float4*>(out + P + o)     = make_float4(aU[d][0], aU[d][1], aU[d][2], aU[d][3]);
        *reinterpret_cast<float4*>(out + 2 * P + o) = make_float4(aV[d][0], aV[d][1], aV[d][2], aV[d][3]);
        *reinterpret_cast<float4*>(out + 3 * P + o) = make_float4(aX[d][0], aX[d][1], aX[d][2], aX[d][3]);
        *reinterpret_cast<float4*>(out + 4 * P + o) = make_float4(aY[d][0], aY[d][1], aY[d][2], aY[d][3]);
    }
}

extern "C" void kernel_launch(void* const* d_in, const int* in_sizes, int n_in,
                              void* d_out, int out_size)
{
    const float* xp = (const float*)d_in[0];
    const float* yp = (const float*)d_in[1];
    // d_in[2] = x_grid, d_in[3] = y_grid: analytic (x, y), not needed.
    const float* vx = (const float*)d_in[4];
    const float* vy = (const float*)d_in[5];
    const float* Fx = (const float*)d_in[6];
    const float* Fy = (const float*)d_in[7];
    const float* mk = (const float*)d_in[8];
    float* out = (float*)d_out;

    // 32 col-blocks x 512 row-blocks; each block: 128 cols x 8 rows of output
    ai4dem_kernel<<<32 * 512, BLK_T>>>(xp, yp, vx, vy, Fx, Fy, mk, out);
}